// round 1
// baseline (speedup 1.0000x reference)
#include <cuda_runtime.h>

// ============================================================================
// LinearAttentionLayer: B=16, N=8192, F=128, U=128, fp32
//   q = exp(x@Wq + bq); k = exp(x@Wk + bk); v = x@Wv + bv
//   kv[b] = k[b]^T @ v[b]  (contract N)
//   out[b] = q[b] @ kv[b]
// Two fused kernels + a zeroing kernel. kv accumulated via atomicAdd into a
// __device__ scratch (16 KB per batch).
// ============================================================================

namespace {
constexpr int Bb = 16;
constexpr int Nn = 8192;
constexpr int Ff = 128;
constexpr int Uu = 128;
constexpr int ROWS_PER_BLOCK = 128;   // rows of N handled per block
constexpr int SUB = 64;               // rows per subtile
constexpr int CHUNKS = Nn / ROWS_PER_BLOCK;  // 64
}

__device__ float g_kv[Bb * Uu * Uu];  // 16 x 128 x 128 fp32 scratch

// Fast exp: range-reduced 2^f with degree-6 Taylor on y = f*ln2, |y| <= 0.347.
// Rel error ~1e-8. Avoids MUFU (rt 8/SMSP would dominate runtime at 33.5M calls).
__device__ __forceinline__ float fexp(float x) {
    float t = x * 1.4426950408889634f;      // x * log2(e)
    float r = t + 12582912.0f;              // 1.5 * 2^23: round-to-nearest int
    int   e = __float_as_int(r) - 0x4B400000;  // integer part
    float f = t - (r - 12582912.0f);        // frac in [-0.5, 0.5]
    float y = f * 0.6931471805599453f;      // back to natural-log domain
    float p = 1.38888894e-3f;               // 1/720
    p = fmaf(p, y, 8.33333377e-3f);         // 1/120
    p = fmaf(p, y, 4.16666679e-2f);         // 1/24
    p = fmaf(p, y, 1.66666672e-1f);         // 1/6
    p = fmaf(p, y, 0.5f);
    p = fmaf(p, y, 1.0f);
    p = fmaf(p, y, 1.0f);
    return __int_as_float(__float_as_int(p) + (e << 23));  // p * 2^e
}

__global__ void zero_kv_kernel() {
    int i = blockIdx.x * blockDim.x + threadIdx.x;   // 256*256 = 65536 float4
    reinterpret_cast<float4*>(g_kv)[i] = make_float4(0.f, 0.f, 0.f, 0.f);
}

// ----------------------------------------------------------------------------
// Kernel 1: kv[b] += exp(X_chunk @ Wk + bk)^T @ (X_chunk @ Wv + bv)
// Block: 256 threads, 128 rows of N, 2 subtiles of 64 rows.
// smem: Wk(64K) + Wv(64K) + X(32K) + K(32K) + V(32K) = 224 KB
// ----------------------------------------------------------------------------
__global__ void __launch_bounds__(256, 1) kv_kernel(
    const float* __restrict__ x,
    const float* __restrict__ Wk, const float* __restrict__ bk,
    const float* __restrict__ Wv, const float* __restrict__ bv)
{
    extern __shared__ float sm[];
    float* sWk = sm;                    // 128*128
    float* sWv = sm + 16384;            // 128*128
    float* sX  = sm + 32768;            // 64*128
    float* sK  = sm + 32768 + 8192;     // 64*128
    float* sV  = sm + 32768 + 16384;    // 64*128

    const int tid   = threadIdx.x;
    const int b     = blockIdx.x >> 6;          // CHUNKS = 64
    const int chunk = blockIdx.x & 63;
    const int n0    = chunk * ROWS_PER_BLOCK;

    // Load weights (float4, coalesced)
    {
        const float4* wk4 = reinterpret_cast<const float4*>(Wk);
        const float4* wv4 = reinterpret_cast<const float4*>(Wv);
        float4* sWk4 = reinterpret_cast<float4*>(sWk);
        float4* sWv4 = reinterpret_cast<float4*>(sWv);
        #pragma unroll
        for (int i = 0; i < 16; ++i) {
            sWk4[tid + 256 * i] = wk4[tid + 256 * i];
            sWv4[tid + 256 * i] = wv4[tid + 256 * i];
        }
    }

    const int ty = tid >> 5;        // 0..7   (row group for projections)
    const int tx = tid & 31;        // 0..31  (col group for projections)
    float bkr[4], bvr[4];
    #pragma unroll
    for (int j = 0; j < 4; ++j) {
        bkr[j] = bk[tx + 32 * j];
        bvr[j] = bv[tx + 32 * j];
    }

    const int tu = tid >> 4;        // 0..15  (u group for kv accumulation)
    const int tw = tid & 15;        // 0..15  (v group)

    float cacc[8][8];
    #pragma unroll
    for (int i = 0; i < 8; ++i)
        #pragma unroll
        for (int j = 0; j < 8; ++j) cacc[i][j] = 0.f;

    const float* xg = x + ((size_t)b * Nn + n0) * Ff;

    for (int s = 0; s < ROWS_PER_BLOCK / SUB; ++s) {
        // --- load 64x128 x subtile ---
        {
            const float4* xs4 = reinterpret_cast<const float4*>(xg + (size_t)s * SUB * Ff);
            float4* sX4 = reinterpret_cast<float4*>(sX);
            #pragma unroll
            for (int i = 0; i < 8; ++i) sX4[tid + 256 * i] = xs4[tid + 256 * i];
        }
        __syncthreads();   // x (and, on s==0, weights) visible; prior accum done

        // --- K projection: k = exp(x @ Wk + bk) ---
        {
            float acc[8][4];
            #pragma unroll
            for (int i = 0; i < 8; ++i)
                #pragma unroll
                for (int j = 0; j < 4; ++j) acc[i][j] = 0.f;
            #pragma unroll 4
            for (int f = 0; f < 128; ++f) {
                float xv[8];
                #pragma unroll
                for (int i = 0; i < 8; ++i) xv[i] = sX[(ty + 8 * i) * 128 + f];
                float w[4];
                #pragma unroll
                for (int j = 0; j < 4; ++j) w[j] = sWk[f * 128 + tx + 32 * j];
                #pragma unroll
                for (int i = 0; i < 8; ++i)
                    #pragma unroll
                    for (int j = 0; j < 4; ++j)
                        acc[i][j] = fmaf(xv[i], w[j], acc[i][j]);
            }
            #pragma unroll
            for (int i = 0; i < 8; ++i)
                #pragma unroll
                for (int j = 0; j < 4; ++j)
                    sK[(ty + 8 * i) * 128 + tx + 32 * j] = fexp(acc[i][j] + bkr[j]);
        }

        // --- V projection: v = x @ Wv + bv ---
        {
            float acc[8][4];
            #pragma unroll
            for (int i = 0; i < 8; ++i)
                #pragma unroll
                for (int j = 0; j < 4; ++j) acc[i][j] = 0.f;
            #pragma unroll 4
            for (int f = 0; f < 128; ++f) {
                float xv[8];
                #pragma unroll
                for (int i = 0; i < 8; ++i) xv[i] = sX[(ty + 8 * i) * 128 + f];
                float w[4];
                #pragma unroll
                for (int j = 0; j < 4; ++j) w[j] = sWv[f * 128 + tx + 32 * j];
                #pragma unroll
                for (int i = 0; i < 8; ++i)
                    #pragma unroll
                    for (int j = 0; j < 4; ++j)
                        acc[i][j] = fmaf(xv[i], w[j], acc[i][j]);
            }
            #pragma unroll
            for (int i = 0; i < 8; ++i)
                #pragma unroll
                for (int j = 0; j < 4; ++j)
                    sV[(ty + 8 * i) * 128 + tx + 32 * j] = acc[i][j] + bvr[j];
        }
        __syncthreads();   // sK/sV ready

        // --- C[u][v] += sum_r sK[r][u] * sV[r][v] ---
        #pragma unroll 2
        for (int r = 0; r < SUB; ++r) {
            float kk[8], vv[8];
            #pragma unroll
            for (int i = 0; i < 8; ++i) kk[i] = sK[r * 128 + tu + 16 * i];
            #pragma unroll
            for (int j = 0; j < 8; ++j) vv[j] = sV[r * 128 + tw + 16 * j];
            #pragma unroll
            for (int i = 0; i < 8; ++i)
                #pragma unroll
                for (int j = 0; j < 8; ++j)
                    cacc[i][j] = fmaf(kk[i], vv[j], cacc[i][j]);
        }
        // no sync needed: next iteration only overwrites sX, and sK/sV writes
        // are guarded by the post-load __syncthreads()
    }

    float* kvb = g_kv + (size_t)b * Uu * Uu;
    #pragma unroll
    for (int i = 0; i < 8; ++i)
        #pragma unroll
        for (int j = 0; j < 8; ++j)
            atomicAdd(&kvb[(tu + 16 * i) * Uu + tw + 16 * j], cacc[i][j]);
}

// ----------------------------------------------------------------------------
// Kernel 2: out[b] = exp(X_chunk @ Wq + bq) @ kv[b]
// smem: Wq(64K) + kv(64K) + X(32K) + Q(32K) = 192 KB
// ----------------------------------------------------------------------------
__global__ void __launch_bounds__(256, 1) out_kernel(
    const float* __restrict__ x,
    const float* __restrict__ Wq, const float* __restrict__ bq,
    float* __restrict__ out)
{
    extern __shared__ float sm[];
    float* sWq = sm;                 // 128*128
    float* sKV = sm + 16384;         // 128*128
    float* sX  = sm + 32768;         // 64*128
    float* sQ  = sm + 40960;         // 64*128

    const int tid   = threadIdx.x;
    const int b     = blockIdx.x >> 6;
    const int chunk = blockIdx.x & 63;
    const int n0    = chunk * ROWS_PER_BLOCK;

    {
        const float4* wq4 = reinterpret_cast<const float4*>(Wq);
        const float4* kv4 = reinterpret_cast<const float4*>(g_kv + (size_t)b * Uu * Uu);
        float4* sWq4 = reinterpret_cast<float4*>(sWq);
        float4* sKV4 = reinterpret_cast<float4*>(sKV);
        #pragma unroll
        for (int i = 0; i < 16; ++i) {
            sWq4[tid + 256 * i] = wq4[tid + 256 * i];
            sKV4[tid + 256 * i] = kv4[tid + 256 * i];
        }
    }

    const int ty = tid >> 5;
    const int tx = tid & 31;
    float bqr[4];
    #pragma unroll
    for (int j = 0; j < 4; ++j) bqr[j] = bq[tx + 32 * j];

    const float* xg = x + ((size_t)b * Nn + n0) * Ff;

    for (int s = 0; s < ROWS_PER_BLOCK / SUB; ++s) {
        {
            const float4* xs4 = reinterpret_cast<const float4*>(xg + (size_t)s * SUB * Ff);
            float4* sX4 = reinterpret_cast<float4*>(sX);
            #pragma unroll
            for (int i = 0; i < 8; ++i) sX4[tid + 256 * i] = xs4[tid + 256 * i];
        }
        __syncthreads();

        // --- Q projection ---
        {
            float acc[8][4];
            #pragma unroll
            for (int i = 0; i < 8; ++i)
                #pragma unroll
                for (int j = 0; j < 4; ++j) acc[i][j] = 0.f;
            #pragma unroll 4
            for (int f = 0; f < 128; ++f) {
                float xv[8];
                #pragma unroll
                for (int i = 0; i < 8; ++i) xv[i] = sX[(ty + 8 * i) * 128 + f];
                float w[4];
                #pragma unroll
                for (int j = 0; j < 4; ++j) w[j] = sWq[f * 128 + tx + 32 * j];
                #pragma unroll
                for (int i = 0; i < 8; ++i)
                    #pragma unroll
                    for (int j = 0; j < 4; ++j)
                        acc[i][j] = fmaf(xv[i], w[j], acc[i][j]);
            }
            #pragma unroll
            for (int i = 0; i < 8; ++i)
                #pragma unroll
                for (int j = 0; j < 4; ++j)
                    sQ[(ty + 8 * i) * 128 + tx + 32 * j] = fexp(acc[i][j] + bqr[j]);
        }
        __syncthreads();

        // --- out = Q @ kv ---
        {
            float acc[8][4];
            #pragma unroll
            for (int i = 0; i < 8; ++i)
                #pragma unroll
                for (int j = 0; j < 4; ++j) acc[i][j] = 0.f;
            #pragma unroll 4
            for (int u = 0; u < 128; ++u) {
                float qv[8];
                #pragma unroll
                for (int i = 0; i < 8; ++i) qv[i] = sQ[(ty + 8 * i) * 128 + u];
                float kv[4];
                #pragma unroll
                for (int j = 0; j < 4; ++j) kv[j] = sKV[u * 128 + tx + 32 * j];
                #pragma unroll
                for (int i = 0; i < 8; ++i)
                    #pragma unroll
                    for (int j = 0; j < 4; ++j)
                        acc[i][j] = fmaf(qv[i], kv[j], acc[i][j]);
            }
            float* og = out + ((size_t)b * Nn + n0 + (size_t)s * SUB) * Uu;
            #pragma unroll
            for (int i = 0; i < 8; ++i)
                #pragma unroll
                for (int j = 0; j < 4; ++j)
                    og[(ty + 8 * i) * Uu + tx + 32 * j] = acc[i][j];
        }
        // next iteration's sX overwrite is guarded by its post-load sync
        // (sQ rewrite guarded by post-load sync as well)
    }
}

// ----------------------------------------------------------------------------
extern "C" void kernel_launch(void* const* d_in, const int* in_sizes, int n_in,
                              void* d_out, int out_size) {
    const float* x  = (const float*)d_in[0];
    const float* Wq = (const float*)d_in[1];
    const float* bq = (const float*)d_in[2];
    const float* Wk = (const float*)d_in[3];
    const float* bk = (const float*)d_in[4];
    const float* Wv = (const float*)d_in[5];
    const float* bv = (const float*)d_in[6];
    float* out = (float*)d_out;

    (void)in_sizes; (void)n_in; (void)out_size;

    constexpr int KV_SMEM  = (16384 * 2 + 8192 * 3) * 4;  // 229376 B
    constexpr int OUT_SMEM = (16384 * 2 + 8192 * 2) * 4;  // 196608 B
    cudaFuncSetAttribute(kv_kernel,  cudaFuncAttributeMaxDynamicSharedMemorySize, KV_SMEM);
    cudaFuncSetAttribute(out_kernel, cudaFuncAttributeMaxDynamicSharedMemorySize, OUT_SMEM);

    zero_kv_kernel<<<256, 256>>>();
    kv_kernel<<<Bb * CHUNKS, 256, KV_SMEM>>>(x, Wk, bk, Wv, bv);
    out_kernel<<<Bb * CHUNKS, 256, OUT_SMEM>>>(x, Wq, bq, out);
}